// round 11
// baseline (speedup 1.0000x reference)
#include <cuda_runtime.h>
#include <cuda_bf16.h>

// Problem shape (fixed by the reference setup_inputs)
#define BB 1024
#define MM 256
#define LL 256

// Single-wave schedule, occupancy-safe:
//   grid (64, 16) = 1024 CTAs; __launch_bounds__(256, 8) forces <=32 regs so
//   all 1024 CTAs are resident in ONE wave (148 SMs x 8 CTAs = 1184 slots).
// Each CTA: fixed ml4 block (4 m-rows), 64 batches as 8 chunks of 8.
// Phi sincos prologue amortizes over 64 stores (vs 8 in the prior kernel).
// Inner 8-iter loop is fully unrolled with immediate-lane shuffles (32-reg body).
#define B_PER_CTA 64
#define B_CHUNK   8

__device__ __forceinline__ float elem(float xv, float sx2, float cx2,
                                      float iv, float niv,
                                      float phv, float cpv, float spv) {
    float diff = xv - phv;                    // identical fp32 op to reference
    bool mask = (diff > niv) & (diff <= iv);  // exact reference semantics
    // val = 0.5*cos(x-phi)+0.5 = cp*(0.5*cx) + sp*(0.5*sx) + 0.5
    float val = fmaf(cpv, cx2, fmaf(spv, sx2, 0.5f));
    return mask ? val : 0.0f;
}

__global__ void __launch_bounds__(256, 8)
bcos_fused_kernel(const float* __restrict__ x,
                  const float* __restrict__ phis,
                  const float* __restrict__ interval,
                  float4* __restrict__ out) {
    int tid   = threadIdx.x;
    int ml4   = blockIdx.x * 256 + tid;    // 0..16383
    int m     = ml4 >> 6;                  // warp-uniform (64 slots per m)
    int lane  = tid & 31;
    int bbase = blockIdx.y * B_PER_CTA;

    float iv  = __ldg(interval + m);
    float niv = -iv;

    // Per-thread phi sincos — once per 64 stores
    float4 ph = reinterpret_cast<const float4*>(phis)[ml4];
    float spx, cpx, spy, cpy, spz, cpz, spw, cpw;
    sincosf(ph.x, &spx, &cpx);
    sincosf(ph.y, &spy, &cpy);
    sincosf(ph.z, &spz, &cpz);
    sincosf(ph.w, &spw, &cpw);

    float4* op = out + (size_t)bbase * (MM * LL / 4) + ml4;

    for (int c = 0; c < B_PER_CTA / B_CHUNK; c++) {
        // Lanes 0..7 (replicated in each 8-lane group) hold x / 0.5*sincos(x)
        // for batches b0..b0+7.
        int b0 = bbase + c * B_CHUNK;
        float my_x = __ldg(x + (b0 + (lane & 7)) * MM + m);
        float s0, c0;
        sincosf(my_x, &s0, &c0);
        float my_s = 0.5f * s0;
        float my_c = 0.5f * c0;

#pragma unroll
        for (int i = 0; i < B_CHUNK; i++) {   // immediate-lane shuffles
            float xv = __shfl_sync(0xffffffffu, my_x, i);
            float s2 = __shfl_sync(0xffffffffu, my_s, i);
            float c2 = __shfl_sync(0xffffffffu, my_c, i);

            float4 o;
            o.x = elem(xv, s2, c2, iv, niv, ph.x, cpx, spx);
            o.y = elem(xv, s2, c2, iv, niv, ph.y, cpy, spy);
            o.z = elem(xv, s2, c2, iv, niv, ph.z, cpz, spz);
            o.w = elem(xv, s2, c2, iv, niv, ph.w, cpw, spw);

            __stcs(op, o);                 // streaming store: don't pollute L2
            op += MM * LL / 4;
        }
    }
}

extern "C" void kernel_launch(void* const* d_in, const int* in_sizes, int n_in,
                              void* d_out, int out_size) {
    const float* x        = (const float*)d_in[0];  // (1024, 256)
    const float* phis     = (const float*)d_in[1];  // (256, 256)
    const float* interval = (const float*)d_in[2];  // (256,)
    float4* out = (float4*)d_out;                   // (1024, 65536) fp32

    dim3 grid(MM * LL / 4 / 256, BB / B_PER_CTA);   // (64, 16) = 1024 CTAs
    bcos_fused_kernel<<<grid, 256>>>(x, phis, interval, out);
}